// round 1
// baseline (speedup 1.0000x reference)
#include <cuda_runtime.h>
#include <math.h>

// Problem constants
#define BB      4
#define CC      192
#define HH      256
#define WWIDTH  256
#define WS      8
#define NHEADS  8
#define HD      24
#define NTOK    64        // tokens per window
#define M3      576       // 3*C
#define NWIN    4096      // total windows
#define TPB     256

// smem layouts (floats), rows 16B-aligned, XOR swizzle on 16B chunks to kill
// the 8-row-stride bank conflicts in the GEMM A-loads.
#define XS_LD   196       // 192 + 4 pad
#define QLD     580       // 576 + 4 pad
#define SMEM_FLOATS (NTOK*XS_LD + NTOK*QLD)   // 12544 + 37120 = 49664 floats = 198656 B

#define XIDX(n,c) ((n)*XS_LD + (((((c)>>2) ^ (((n)>>3)&7)))<<2) + ((c)&3))
#define QIDX(n,m) ((n)*QLD  + (((((m)>>2) ^ (((n)>>3)&7)))<<2) + ((m)&3))

// Precomputed relative-position bias (16*sigmoid folded) and per-head scale.
__device__ float g_bias[NHEADS * NTOK * NTOK];   // 128 KB, L2-resident
__device__ float g_scale[NHEADS];

// ---------------------------------------------------------------------------
// Kernel A: CPB MLP -> bias table + logit scales. Tiny; one block.
// ---------------------------------------------------------------------------
__global__ void cpb_kernel(const float* __restrict__ cpb_w1,
                           const float* __restrict__ cpb_b1,
                           const float* __restrict__ cpb_w2,
                           const float* __restrict__ logit_scale) {
    __shared__ float tbl[225 * NHEADS];
    int tid = threadIdx.x;

    if (tid < 225) {
        int a = tid / 15, b = tid % 15;
        float t0 = (float)(a - 7) * (8.0f / 7.0f);
        float t1 = (float)(b - 7) * (8.0f / 7.0f);
        // sign(t) * log2(|t|+1) / log2(8)
        t0 = copysignf(log2f(fabsf(t0) + 1.0f) * (1.0f / 3.0f), t0);
        t1 = copysignf(log2f(fabsf(t1) + 1.0f) * (1.0f / 3.0f), t1);
        float o[NHEADS];
        #pragma unroll
        for (int h = 0; h < NHEADS; ++h) o[h] = 0.0f;
        for (int j = 0; j < 512; ++j) {
            float hdn = fmaf(t0, cpb_w1[j], fmaf(t1, cpb_w1[512 + j], cpb_b1[j]));
            hdn = fmaxf(hdn, 0.0f);
            #pragma unroll
            for (int h = 0; h < NHEADS; ++h) o[h] = fmaf(hdn, cpb_w2[j * NHEADS + h], o[h]);
        }
        #pragma unroll
        for (int h = 0; h < NHEADS; ++h) tbl[tid * NHEADS + h] = o[h];
    }
    if (tid < NHEADS) {
        g_scale[tid] = expf(fminf(logit_scale[tid], 4.6051701859880914f)); // log(100)
    }
    __syncthreads();

    for (int e = tid; e < NHEADS * NTOK * NTOK; e += blockDim.x) {
        int h = e / (NTOK * NTOK);
        int r = (e / NTOK) & 63;
        int m = e & 63;
        int di = (r >> 3) - (m >> 3) + 7;
        int dj = (r & 7) - (m & 7) + 7;
        float v = tbl[(di * 15 + dj) * NHEADS + h];
        g_bias[e] = 16.0f / (1.0f + __expf(-v));
    }
}

// ---------------------------------------------------------------------------
// Kernel B: fused window attention. One CTA per window, 256 threads.
// ---------------------------------------------------------------------------
__global__ void __launch_bounds__(TPB, 1)
win_attn_kernel(const float* __restrict__ x,
                const float* __restrict__ qkv_w,     // (576,192) row-major
                const float* __restrict__ q_bias,    // (192)
                const float* __restrict__ v_bias,    // (192)
                const float* __restrict__ proj_w,    // (192,192) row-major
                const float* __restrict__ proj_b,    // (192)
                float* __restrict__ out) {
    extern __shared__ float sm[];
    float* xs = sm;                       // NTOK x XS_LD (input window, for GEMM A + residual)
    float* qs = sm + NTOK * XS_LD;        // NTOK x QLD  (q|k|v, then O overwrites q)

    const int tid  = threadIdx.x;
    const int warp = tid >> 5;
    const int lane = tid & 31;

    const int wi  = blockIdx.x;
    const int b   = wi >> 10;
    const int rem = wi & 1023;
    const int y0  = (rem >> 5) << 3;
    const int x0  = (rem & 31) << 3;

    // ---- Stage input window into smem ----
    const float* xbase = x + (size_t)b * CC * HH * WWIDTH;
    for (int e = tid; e < NTOK * CC; e += TPB) {
        int c = e >> 6;
        int n = e & 63;
        float v = xbase[((size_t)c * HH + (y0 + (n >> 3))) * WWIDTH + (x0 + (n & 7))];
        xs[XIDX(n, c)] = v;
    }
    __syncthreads();

    // ---- QKV GEMM: qs[n][m] = sum_c xs[n][c] * qkv_w[m][c] + bias[m] ----
    // warp owns m in [warp*72, warp*72+72): W read exactly once per CTA.
    {
        const int ln = lane >> 2;          // 0..7  -> n block of 8
        const int lc = lane & 3;           // 0..3  -> m sub-block
        const int nb = ln << 3;
        #pragma unroll
        for (int s = 0; s < 3; ++s) {
            const int mbase = warp * 72 + s * 24 + lc * 6;
            float acc[8][6];
            #pragma unroll
            for (int i = 0; i < 8; ++i)
                #pragma unroll
                for (int j = 0; j < 6; ++j) acc[i][j] = 0.0f;

            #pragma unroll 2
            for (int c = 0; c < CC; c += 4) {
                float4 a4[8];
                #pragma unroll
                for (int i = 0; i < 8; ++i)
                    a4[i] = *(const float4*)(xs + QIDX(0,0)*0 + XIDX(nb + i, c));
                float4 b4[6];
                #pragma unroll
                for (int j = 0; j < 6; ++j)
                    b4[j] = *(const float4*)(qkv_w + (size_t)(mbase + j) * CC + c);
                #pragma unroll
                for (int i = 0; i < 8; ++i) {
                    #pragma unroll
                    for (int j = 0; j < 6; ++j) {
                        acc[i][j] = fmaf(a4[i].x, b4[j].x, acc[i][j]);
                        acc[i][j] = fmaf(a4[i].y, b4[j].y, acc[i][j]);
                        acc[i][j] = fmaf(a4[i].z, b4[j].z, acc[i][j]);
                        acc[i][j] = fmaf(a4[i].w, b4[j].w, acc[i][j]);
                    }
                }
            }
            #pragma unroll
            for (int j = 0; j < 6; ++j) {
                const int m = mbase + j;
                float bia = (m < 192) ? q_bias[m] : ((m >= 384) ? v_bias[m - 384] : 0.0f);
                #pragma unroll
                for (int i = 0; i < 8; ++i)
                    qs[QIDX(nb + i, m)] = acc[i][j] + bia;
            }
        }
    }
    __syncthreads();

    // ---- Attention: one warp per head ----
    {
        const int h   = warp;
        const int qo  = h * HD;          // q cols
        const int ko  = 192 + h * HD;    // k cols
        const int vo  = 384 + h * HD;    // v cols
        const float sc = g_scale[h];

        // normalize: fold scale into q; each lane handles rows lane, lane+32
        #pragma unroll
        for (int rr = 0; rr < 2; ++rr) {
            const int n = lane + (rr << 5);
            float ss = 0.0f;
            #pragma unroll
            for (int d = 0; d < HD; ++d) { float v = qs[QIDX(n, qo + d)]; ss = fmaf(v, v, ss); }
            float inv = sc / fmaxf(sqrtf(ss), 1e-12f);
            #pragma unroll
            for (int d = 0; d < HD; ++d) qs[QIDX(n, qo + d)] *= inv;
            ss = 0.0f;
            #pragma unroll
            for (int d = 0; d < HD; ++d) { float v = qs[QIDX(n, ko + d)]; ss = fmaf(v, v, ss); }
            inv = 1.0f / fmaxf(sqrtf(ss), 1e-12f);
            #pragma unroll
            for (int d = 0; d < HD; ++d) qs[QIDX(n, ko + d)] *= inv;
        }
        __syncwarp();

        // single-pass softmax: scores <= sc*1 + 16, so shift by ub (no overflow,
        // no underflow for sc = O(10..100)). Lane handles rows 2*lane, 2*lane+1.
        const float ub = sc + 16.0f;
        const float* bias_h = g_bias + h * NTOK * NTOK;

        #pragma unroll
        for (int rr = 0; rr < 2; ++rr) {
            const int r = (lane << 1) + rr;
            float qr[HD];
            #pragma unroll
            for (int t = 0; t < 6; ++t)
                *(float4*)(qr + 4 * t) = *(const float4*)(qs + QIDX(r, qo + 4 * t));

            float o[HD];
            #pragma unroll
            for (int d = 0; d < HD; ++d) o[d] = 0.0f;
            float psum = 0.0f;

            #pragma unroll 2
            for (int m = 0; m < NTOK; ++m) {
                float acc = bias_h[r * NTOK + m] - ub;
                #pragma unroll
                for (int t = 0; t < 6; ++t) {
                    float4 kv = *(const float4*)(qs + QIDX(m, ko + 4 * t));
                    acc = fmaf(qr[4 * t + 0], kv.x, acc);
                    acc = fmaf(qr[4 * t + 1], kv.y, acc);
                    acc = fmaf(qr[4 * t + 2], kv.z, acc);
                    acc = fmaf(qr[4 * t + 3], kv.w, acc);
                }
                float p = __expf(acc);
                psum += p;
                #pragma unroll
                for (int t = 0; t < 6; ++t) {
                    float4 vv = *(const float4*)(qs + QIDX(m, vo + 4 * t));
                    o[4 * t + 0] = fmaf(p, vv.x, o[4 * t + 0]);
                    o[4 * t + 1] = fmaf(p, vv.y, o[4 * t + 1]);
                    o[4 * t + 2] = fmaf(p, vv.z, o[4 * t + 2]);
                    o[4 * t + 3] = fmaf(p, vv.w, o[4 * t + 3]);
                }
            }
            const float invs = 1.0f / psum;
            // overwrite q region with O (only this lane ever reads its q rows)
            #pragma unroll
            for (int d = 0; d < HD; ++d) qs[QIDX(r, qo + d)] = o[d] * invs;
        }
    }
    __syncthreads();

    // ---- Proj GEMM + residual + store: out[n][c] = sum_cc O[n][cc]*proj_w[c][cc] + b[c] + x[n][c]
    {
        const int ln = lane >> 2;
        const int lc = lane & 3;
        const int nb = ln << 3;
        const int cbase = warp * 24 + lc * 6;

        float acc[8][6];
        #pragma unroll
        for (int i = 0; i < 8; ++i)
            #pragma unroll
            for (int j = 0; j < 6; ++j) acc[i][j] = 0.0f;

        #pragma unroll 2
        for (int c = 0; c < CC; c += 4) {
            float4 a4[8];
            #pragma unroll
            for (int i = 0; i < 8; ++i)
                a4[i] = *(const float4*)(qs + QIDX(nb + i, c));
            float4 b4[6];
            #pragma unroll
            for (int j = 0; j < 6; ++j)
                b4[j] = *(const float4*)(proj_w + (size_t)(cbase + j) * CC + c);
            #pragma unroll
            for (int i = 0; i < 8; ++i) {
                #pragma unroll
                for (int j = 0; j < 6; ++j) {
                    acc[i][j] = fmaf(a4[i].x, b4[j].x, acc[i][j]);
                    acc[i][j] = fmaf(a4[i].y, b4[j].y, acc[i][j]);
                    acc[i][j] = fmaf(a4[i].z, b4[j].z, acc[i][j]);
                    acc[i][j] = fmaf(a4[i].w, b4[j].w, acc[i][j]);
                }
            }
        }

        #pragma unroll
        for (int j = 0; j < 6; ++j) {
            const int cc = cbase + j;
            const float pb = proj_b[cc];
            float* obase = out + ((size_t)b * CC + cc) * HH * WWIDTH;
            #pragma unroll
            for (int i = 0; i < 8; ++i) {
                const int n = nb + i;
                float v = acc[i][j] + pb + xs[XIDX(n, cc)];
                obase[(size_t)(y0 + (n >> 3)) * WWIDTH + (x0 + (n & 7))] = v;
            }
        }
    }
}

// ---------------------------------------------------------------------------
extern "C" void kernel_launch(void* const* d_in, const int* in_sizes, int n_in,
                              void* d_out, int out_size) {
    (void)in_sizes; (void)n_in; (void)out_size;
    const float* x           = (const float*)d_in[0];
    // d_in[1] img_alpha: unused (all-ones, shift_size==0 path is a no-op)
    const float* qkv_w       = (const float*)d_in[2];
    const float* q_bias      = (const float*)d_in[3];
    const float* v_bias      = (const float*)d_in[4];
    const float* logit_scale = (const float*)d_in[5];
    const float* cpb_w1      = (const float*)d_in[6];
    const float* cpb_b1      = (const float*)d_in[7];
    const float* cpb_w2      = (const float*)d_in[8];
    const float* proj_w      = (const float*)d_in[9];
    const float* proj_b      = (const float*)d_in[10];
    float* out = (float*)d_out;

    cpb_kernel<<<1, 256>>>(cpb_w1, cpb_b1, cpb_w2, logit_scale);

    const size_t smem = (size_t)SMEM_FLOATS * sizeof(float);   // 198656 B
    cudaFuncSetAttribute(win_attn_kernel,
                         cudaFuncAttributeMaxDynamicSharedMemorySize, (int)smem);
    win_attn_kernel<<<NWIN, TPB, smem>>>(x, qkv_w, q_bias, v_bias, proj_w, proj_b, out);
}

// round 2
// speedup vs baseline: 1.0027x; 1.0027x over previous
#include <cuda_runtime.h>
#include <math.h>

// Problem constants
#define BB      4
#define CC      192
#define HH      256
#define WWIDTH  256
#define WS      8
#define NHEADS  8
#define HD      24
#define NTOK    64        // tokens per window
#define M3      576       // 3*C
#define NWIN    4096      // total windows
#define TPB     256

// smem layouts (floats), rows 16B-aligned, XOR swizzle on 16B chunks to kill
// the 8-row-stride bank conflicts in the GEMM A-loads.
#define XS_LD   196       // 192 + 4 pad
#define QLD     580       // 576 + 4 pad
#define SMEM_FLOATS (NTOK*XS_LD + NTOK*QLD)   // 12544 + 37120 = 49664 floats = 198656 B

#define XIDX(n,c) ((n)*XS_LD + (((((c)>>2) ^ (((n)>>3)&7)))<<2) + ((c)&3))
#define QIDX(n,m) ((n)*QLD  + (((((m)>>2) ^ (((n)>>3)&7)))<<2) + ((m)&3))

// Precomputed relative-position bias (16*sigmoid folded) and per-head scale.
__device__ float g_bias[NHEADS * NTOK * NTOK];   // 128 KB, L2-resident
__device__ float g_scale[NHEADS];

// ---------------------------------------------------------------------------
// Kernel A: CPB MLP -> bias table + logit scales. Tiny; one block.
// ---------------------------------------------------------------------------
__global__ void cpb_kernel(const float* __restrict__ cpb_w1,
                           const float* __restrict__ cpb_b1,
                           const float* __restrict__ cpb_w2,
                           const float* __restrict__ logit_scale) {
    __shared__ float tbl[225 * NHEADS];
    int tid = threadIdx.x;

    if (tid < 225) {
        int a = tid / 15, b = tid % 15;
        float t0 = (float)(a - 7) * (8.0f / 7.0f);
        float t1 = (float)(b - 7) * (8.0f / 7.0f);
        // sign(t) * log2(|t|+1) / log2(8)
        t0 = copysignf(log2f(fabsf(t0) + 1.0f) * (1.0f / 3.0f), t0);
        t1 = copysignf(log2f(fabsf(t1) + 1.0f) * (1.0f / 3.0f), t1);
        float o[NHEADS];
        #pragma unroll
        for (int h = 0; h < NHEADS; ++h) o[h] = 0.0f;
        for (int j = 0; j < 512; ++j) {
            float hdn = fmaf(t0, cpb_w1[j], fmaf(t1, cpb_w1[512 + j], cpb_b1[j]));
            hdn = fmaxf(hdn, 0.0f);
            #pragma unroll
            for (int h = 0; h < NHEADS; ++h) o[h] = fmaf(hdn, cpb_w2[j * NHEADS + h], o[h]);
        }
        #pragma unroll
        for (int h = 0; h < NHEADS; ++h) tbl[tid * NHEADS + h] = o[h];
    }
    if (tid < NHEADS) {
        g_scale[tid] = expf(fminf(logit_scale[tid], 4.6051701859880914f)); // log(100)
    }
    __syncthreads();

    for (int e = tid; e < NHEADS * NTOK * NTOK; e += blockDim.x) {
        int h = e / (NTOK * NTOK);
        int r = (e / NTOK) & 63;
        int m = e & 63;
        int di = (r >> 3) - (m >> 3) + 7;
        int dj = (r & 7) - (m & 7) + 7;
        float v = tbl[(di * 15 + dj) * NHEADS + h];
        g_bias[e] = 16.0f / (1.0f + __expf(-v));
    }
}

// ---------------------------------------------------------------------------
// Kernel B: fused window attention. One CTA per window, 256 threads.
// ---------------------------------------------------------------------------
__global__ void __launch_bounds__(TPB, 1)
win_attn_kernel(const float* __restrict__ x,
                const float* __restrict__ qkv_w,     // (576,192) row-major
                const float* __restrict__ q_bias,    // (192)
                const float* __restrict__ v_bias,    // (192)
                const float* __restrict__ proj_w,    // (192,192) row-major
                const float* __restrict__ proj_b,    // (192)
                float* __restrict__ out) {
    extern __shared__ float sm[];
    float* xs = sm;                       // NTOK x XS_LD (input window, for GEMM A + residual)
    float* qs = sm + NTOK * XS_LD;        // NTOK x QLD  (q|k|v, then O overwrites q)

    const int tid  = threadIdx.x;
    const int warp = tid >> 5;
    const int lane = tid & 31;

    const int wi  = blockIdx.x;
    const int b   = wi >> 10;
    const int rem = wi & 1023;
    const int y0  = (rem >> 5) << 3;
    const int x0  = (rem & 31) << 3;

    // ---- Stage input window into smem ----
    const float* xbase = x + (size_t)b * CC * HH * WWIDTH;
    for (int e = tid; e < NTOK * CC; e += TPB) {
        int c = e >> 6;
        int n = e & 63;
        float v = xbase[((size_t)c * HH + (y0 + (n >> 3))) * WWIDTH + (x0 + (n & 7))];
        xs[XIDX(n, c)] = v;
    }
    __syncthreads();

    // ---- QKV GEMM: qs[n][m] = sum_c xs[n][c] * qkv_w[m][c] + bias[m] ----
    // warp owns m in [warp*72, warp*72+72): W read exactly once per CTA.
    {
        const int ln = lane >> 2;          // 0..7  -> n block of 8
        const int lc = lane & 3;           // 0..3  -> m sub-block
        const int nb = ln << 3;
        #pragma unroll
        for (int s = 0; s < 3; ++s) {
            const int mbase = warp * 72 + s * 24 + lc * 6;
            float acc[8][6];
            #pragma unroll
            for (int i = 0; i < 8; ++i)
                #pragma unroll
                for (int j = 0; j < 6; ++j) acc[i][j] = 0.0f;

            #pragma unroll 2
            for (int c = 0; c < CC; c += 4) {
                float4 a4[8];
                #pragma unroll
                for (int i = 0; i < 8; ++i)
                    a4[i] = *(const float4*)(xs + QIDX(0,0)*0 + XIDX(nb + i, c));
                float4 b4[6];
                #pragma unroll
                for (int j = 0; j < 6; ++j)
                    b4[j] = *(const float4*)(qkv_w + (size_t)(mbase + j) * CC + c);
                #pragma unroll
                for (int i = 0; i < 8; ++i) {
                    #pragma unroll
                    for (int j = 0; j < 6; ++j) {
                        acc[i][j] = fmaf(a4[i].x, b4[j].x, acc[i][j]);
                        acc[i][j] = fmaf(a4[i].y, b4[j].y, acc[i][j]);
                        acc[i][j] = fmaf(a4[i].z, b4[j].z, acc[i][j]);
                        acc[i][j] = fmaf(a4[i].w, b4[j].w, acc[i][j]);
                    }
                }
            }
            #pragma unroll
            for (int j = 0; j < 6; ++j) {
                const int m = mbase + j;
                float bia = (m < 192) ? q_bias[m] : ((m >= 384) ? v_bias[m - 384] : 0.0f);
                #pragma unroll
                for (int i = 0; i < 8; ++i)
                    qs[QIDX(nb + i, m)] = acc[i][j] + bia;
            }
        }
    }
    __syncthreads();

    // ---- Attention: one warp per head ----
    {
        const int h   = warp;
        const int qo  = h * HD;          // q cols
        const int ko  = 192 + h * HD;    // k cols
        const int vo  = 384 + h * HD;    // v cols
        const float sc = g_scale[h];

        // normalize: fold scale into q; each lane handles rows lane, lane+32
        #pragma unroll
        for (int rr = 0; rr < 2; ++rr) {
            const int n = lane + (rr << 5);
            float ss = 0.0f;
            #pragma unroll
            for (int d = 0; d < HD; ++d) { float v = qs[QIDX(n, qo + d)]; ss = fmaf(v, v, ss); }
            float inv = sc / fmaxf(sqrtf(ss), 1e-12f);
            #pragma unroll
            for (int d = 0; d < HD; ++d) qs[QIDX(n, qo + d)] *= inv;
            ss = 0.0f;
            #pragma unroll
            for (int d = 0; d < HD; ++d) { float v = qs[QIDX(n, ko + d)]; ss = fmaf(v, v, ss); }
            inv = 1.0f / fmaxf(sqrtf(ss), 1e-12f);
            #pragma unroll
            for (int d = 0; d < HD; ++d) qs[QIDX(n, ko + d)] *= inv;
        }
        __syncwarp();

        // single-pass softmax: scores <= sc*1 + 16, so shift by ub (no overflow,
        // no underflow for sc = O(10..100)). Lane handles rows 2*lane, 2*lane+1.
        const float ub = sc + 16.0f;
        const float* bias_h = g_bias + h * NTOK * NTOK;

        #pragma unroll
        for (int rr = 0; rr < 2; ++rr) {
            const int r = (lane << 1) + rr;
            float qr[HD];
            #pragma unroll
            for (int t = 0; t < 6; ++t)
                *(float4*)(qr + 4 * t) = *(const float4*)(qs + QIDX(r, qo + 4 * t));

            float o[HD];
            #pragma unroll
            for (int d = 0; d < HD; ++d) o[d] = 0.0f;
            float psum = 0.0f;

            #pragma unroll 2
            for (int m = 0; m < NTOK; ++m) {
                float acc = bias_h[r * NTOK + m] - ub;
                #pragma unroll
                for (int t = 0; t < 6; ++t) {
                    float4 kv = *(const float4*)(qs + QIDX(m, ko + 4 * t));
                    acc = fmaf(qr[4 * t + 0], kv.x, acc);
                    acc = fmaf(qr[4 * t + 1], kv.y, acc);
                    acc = fmaf(qr[4 * t + 2], kv.z, acc);
                    acc = fmaf(qr[4 * t + 3], kv.w, acc);
                }
                float p = __expf(acc);
                psum += p;
                #pragma unroll
                for (int t = 0; t < 6; ++t) {
                    float4 vv = *(const float4*)(qs + QIDX(m, vo + 4 * t));
                    o[4 * t + 0] = fmaf(p, vv.x, o[4 * t + 0]);
                    o[4 * t + 1] = fmaf(p, vv.y, o[4 * t + 1]);
                    o[4 * t + 2] = fmaf(p, vv.z, o[4 * t + 2]);
                    o[4 * t + 3] = fmaf(p, vv.w, o[4 * t + 3]);
                }
            }
            const float invs = 1.0f / psum;
            // overwrite q region with O (only this lane ever reads its q rows)
            #pragma unroll
            for (int d = 0; d < HD; ++d) qs[QIDX(r, qo + d)] = o[d] * invs;
        }
    }
    __syncthreads();

    // ---- Proj GEMM + residual + store: out[n][c] = sum_cc O[n][cc]*proj_w[c][cc] + b[c] + x[n][c]
    {
        const int ln = lane >> 2;
        const int lc = lane & 3;
        const int nb = ln << 3;
        const int cbase = warp * 24 + lc * 6;

        float acc[8][6];
        #pragma unroll
        for (int i = 0; i < 8; ++i)
            #pragma unroll
            for (int j = 0; j < 6; ++j) acc[i][j] = 0.0f;

        #pragma unroll 2
        for (int c = 0; c < CC; c += 4) {
            float4 a4[8];
            #pragma unroll
            for (int i = 0; i < 8; ++i)
                a4[i] = *(const float4*)(qs + QIDX(nb + i, c));
            float4 b4[6];
            #pragma unroll
            for (int j = 0; j < 6; ++j)
                b4[j] = *(const float4*)(proj_w + (size_t)(cbase + j) * CC + c);
            #pragma unroll
            for (int i = 0; i < 8; ++i) {
                #pragma unroll
                for (int j = 0; j < 6; ++j) {
                    acc[i][j] = fmaf(a4[i].x, b4[j].x, acc[i][j]);
                    acc[i][j] = fmaf(a4[i].y, b4[j].y, acc[i][j]);
                    acc[i][j] = fmaf(a4[i].z, b4[j].z, acc[i][j]);
                    acc[i][j] = fmaf(a4[i].w, b4[j].w, acc[i][j]);
                }
            }
        }

        #pragma unroll
        for (int j = 0; j < 6; ++j) {
            const int cc = cbase + j;
            const float pb = proj_b[cc];
            float* obase = out + ((size_t)b * CC + cc) * HH * WWIDTH;
            #pragma unroll
            for (int i = 0; i < 8; ++i) {
                const int n = nb + i;
                float v = acc[i][j] + pb + xs[XIDX(n, cc)];
                obase[(size_t)(y0 + (n >> 3)) * WWIDTH + (x0 + (n & 7))] = v;
            }
        }
    }
}

// ---------------------------------------------------------------------------
extern "C" void kernel_launch(void* const* d_in, const int* in_sizes, int n_in,
                              void* d_out, int out_size) {
    (void)in_sizes; (void)n_in; (void)out_size;
    const float* x           = (const float*)d_in[0];
    // d_in[1] img_alpha: unused (all-ones, shift_size==0 path is a no-op)
    const float* qkv_w       = (const float*)d_in[2];
    const float* q_bias      = (const float*)d_in[3];
    const float* v_bias      = (const float*)d_in[4];
    const float* logit_scale = (const float*)d_in[5];
    const float* cpb_w1      = (const float*)d_in[6];
    const float* cpb_b1      = (const float*)d_in[7];
    const float* cpb_w2      = (const float*)d_in[8];
    const float* proj_w      = (const float*)d_in[9];
    const float* proj_b      = (const float*)d_in[10];
    float* out = (float*)d_out;

    cpb_kernel<<<1, 256>>>(cpb_w1, cpb_b1, cpb_w2, logit_scale);

    const size_t smem = (size_t)SMEM_FLOATS * sizeof(float);   // 198656 B
    cudaFuncSetAttribute(win_attn_kernel,
                         cudaFuncAttributeMaxDynamicSharedMemorySize, (int)smem);
    win_attn_kernel<<<NWIN, TPB, smem>>>(x, qkv_w, q_bias, v_bias, proj_w, proj_b, out);
}